// round 10
// baseline (speedup 1.0000x reference)
#include <cuda_runtime.h>
#include <cuda_bf16.h>
#include <cstdint>
#include <cstddef>

// Problem constants
#define NN 100000
#define NE 600000
#define DIM 128
#define NT 782                     // ceil(NN/128)
#define PADN (NT * 128)            // 100096 padded rows
#define PFEATS (PADN * DIM)

// ---------------------------------------------------------------------------
// Device scratch (static — no runtime allocation)
// ---------------------------------------------------------------------------
__device__ __align__(16) float g_ha[PFEATS];
__device__ __align__(16) float g_hb[PFEATS];
__device__ __nv_bfloat16 g_w1hi[DIM * DIM];   // W^T [n][k] bf16 hi
__device__ __nv_bfloat16 g_w1lo[DIM * DIM];
__device__ __nv_bfloat16 g_w2hi[DIM * DIM];
__device__ __nv_bfloat16 g_w2lo[DIM * DIM];
__device__ int g_deg[NN];
__device__ int g_cursor[NN];
__device__ int g_rowstart[NN + 1];
__device__ int g_csr_src[NE];

// ---------------------------------------------------------------------------
// CSR build (validated)
// ---------------------------------------------------------------------------
__global__ void clear_counts_kernel() {
    int i = blockIdx.x * blockDim.x + threadIdx.x;
    if (i < NN) { g_deg[i] = 0; g_cursor[i] = 0; }
}
__global__ void hist_kernel(const int* __restrict__ dst) {
    int e = blockIdx.x * blockDim.x + threadIdx.x;
    if (e < NE) atomicAdd(&g_deg[dst[e]], 1);
}
#define SCHUNK 98
__global__ void scan_kernel() {
    __shared__ int part[1024];
    int t = threadIdx.x;
    int start = t * SCHUNK;
    int end = min(start + SCHUNK, NN);
    int s = 0;
    for (int i = start; i < end; i++) s += g_deg[i];
    part[t] = s;
    __syncthreads();
    for (int off = 1; off < 1024; off <<= 1) {
        int v = (t >= off) ? part[t - off] : 0;
        __syncthreads();
        part[t] += v;
        __syncthreads();
    }
    int run = (t == 0) ? 0 : part[t - 1];
    for (int i = start; i < end; i++) { g_rowstart[i] = run; run += g_deg[i]; }
    if (t == 1023) g_rowstart[NN] = part[1023];
}
__global__ void fill_kernel(const int* __restrict__ src, const int* __restrict__ dst) {
    int e = blockIdx.x * blockDim.x + threadIdx.x;
    if (e < NE) {
        int v = dst[e];
        int pos = g_rowstart[v] + atomicAdd(&g_cursor[v], 1);
        g_csr_src[pos] = src[e];
    }
}

// ---------------------------------------------------------------------------
// Weight prep: W[k][n] fp32 -> W^T[n][k] bf16 hi/lo
// ---------------------------------------------------------------------------
__global__ void wprep_kernel(const float* __restrict__ W,
                             __nv_bfloat16* __restrict__ Hi,
                             __nv_bfloat16* __restrict__ Lo) {
    int idx = blockIdx.x * blockDim.x + threadIdx.x;
    if (idx >= DIM * DIM) return;
    int k = idx >> 7, n = idx & 127;
    float v = W[idx];
    __nv_bfloat16 h = __float2bfloat16(v);
    __nv_bfloat16 l = __float2bfloat16(v - __bfloat162float(h));
    Hi[n * DIM + k] = h;
    Lo[n * DIM + k] = l;
}

// ---------------------------------------------------------------------------
// mma.sync helpers (validated in round 7)
// ---------------------------------------------------------------------------
#define PITCH 272                          // padded smem row: 136 bf16 = 272 B
#define SM_AHI 0                           // A tile hi  (reused for hid hi)
#define SM_ALO (128 * PITCH)               // A tile lo  (reused for hid lo)
#define SM_W1HI (2 * 128 * PITCH)
#define SM_W1LO (3 * 128 * PITCH)
#define SM_W2HI (4 * 128 * PITCH)
#define SM_W2LO (5 * 128 * PITCH)
#define SMEM_DYN (6 * 128 * PITCH)         // 208896 B

static __device__ __forceinline__ uint32_t smem_u32(const void* p) {
    uint32_t a;
    asm("{ .reg .u64 t; cvta.to.shared.u64 t, %1; cvt.u32.u64 %0, t; }" : "=r"(a) : "l"(p));
    return a;
}
static __device__ __forceinline__ void ldm_x4(uint32_t* r, uint32_t addr) {
    asm volatile("ldmatrix.sync.aligned.m8n8.x4.shared.b16 {%0,%1,%2,%3}, [%4];"
                 : "=r"(r[0]), "=r"(r[1]), "=r"(r[2]), "=r"(r[3]) : "r"(addr));
}
static __device__ __forceinline__ void ldm_x2(uint32_t* r, uint32_t addr) {
    asm volatile("ldmatrix.sync.aligned.m8n8.x2.shared.b16 {%0,%1}, [%2];"
                 : "=r"(r[0]), "=r"(r[1]) : "r"(addr));
}
static __device__ __forceinline__ void mma_bf16(float* d, const uint32_t* a, const uint32_t* b) {
    asm volatile(
        "mma.sync.aligned.m16n8k16.row.col.f32.bf16.bf16.f32 "
        "{%0,%1,%2,%3}, {%4,%5,%6,%7}, {%8,%9}, {%0,%1,%2,%3};"
        : "+f"(d[0]), "+f"(d[1]), "+f"(d[2]), "+f"(d[3])
        : "r"(a[0]), "r"(a[1]), "r"(a[2]), "r"(a[3]), "r"(b[0]), "r"(b[1]));
}
static __device__ __forceinline__ void split_pack(float a, float b, uint32_t& hi, uint32_t& lo) {
    __nv_bfloat16 ha = __float2bfloat16(a), hb = __float2bfloat16(b);
    __nv_bfloat16 la = __float2bfloat16(a - __bfloat162float(ha));
    __nv_bfloat16 lb = __float2bfloat16(b - __bfloat162float(hb));
    __nv_bfloat162 H; H.x = ha; H.y = hb;
    __nv_bfloat162 L; L.x = la; L.y = lb;
    hi = *(uint32_t*)&H; lo = *(uint32_t*)&L;
}

// 3-pass split-fp32 GEMM core: warp tile 32(M) x 32(N), K=128.
// acc += A_hi*W_hi + A_hi*W_lo + A_lo*W_hi
static __device__ __forceinline__ void gemm3pass(
    uint32_t sAhi, uint32_t sAlo, uint32_t sWhi, uint32_t sWlo,
    float acc[2][4][4]) {
#pragma unroll
    for (int pass = 0; pass < 3; pass++) {
        uint32_t sA = (pass == 2) ? sAlo : sAhi;
        uint32_t sW = (pass == 1) ? sWlo : sWhi;
#pragma unroll
        for (int k0 = 0; k0 < 128; k0 += 16) {
            uint32_t af[2][4], bf[4][2];
            ldm_x4(af[0], sA + k0 * 2);
            ldm_x4(af[1], sA + 16 * PITCH + k0 * 2);
#pragma unroll
            for (int nj = 0; nj < 4; nj++)
                ldm_x2(bf[nj], sW + nj * 8 * PITCH + k0 * 2);
#pragma unroll
            for (int mi = 0; mi < 2; mi++)
#pragma unroll
                for (int nj = 0; nj < 4; nj++)
                    mma_bf16(acc[mi][nj], af[mi], bf[nj]);
        }
    }
}

// ---------------------------------------------------------------------------
// Fused layer kernel: gather + split -> GEMM1(+b1,ReLU) -> hid in smem ->
// GEMM2(+b2,opt ReLU) -> global. One CTA per 128-row tile, 512 threads.
// ---------------------------------------------------------------------------
__global__ void __launch_bounds__(512, 1)
fused_layer_kernel(const float* __restrict__ Hin,
                   const __nv_bfloat16* __restrict__ W1h, const __nv_bfloat16* __restrict__ W1l,
                   const __nv_bfloat16* __restrict__ W2h, const __nv_bfloat16* __restrict__ W2l,
                   const float* __restrict__ b1, const float* __restrict__ b2,
                   float* __restrict__ Hout, int outRows, int doRelu2) {
    extern __shared__ __align__(16) unsigned char smem[];
    uint32_t sbase = smem_u32(smem);
    int tid = threadIdx.x, wid = tid >> 5, lane = tid & 31;
    int rowbase = blockIdx.x * 128;

    // ---- Load weights (bf16 hi/lo, pre-transposed) into padded smem ----
    {
        const uint4* srcs[4] = {(const uint4*)W1h, (const uint4*)W1l,
                                (const uint4*)W2h, (const uint4*)W2l};
        const uint32_t offs[4] = {SM_W1HI, SM_W1LO, SM_W2HI, SM_W2LO};
#pragma unroll
        for (int b = 0; b < 4; b++) {
#pragma unroll
            for (int i = 0; i < 4; i++) {
                int idx = tid + i * 512;        // 2048 uint4 = 128x16
                int row = idx >> 4, c = idx & 15;
                *(uint4*)(smem + offs[b] + row * PITCH + c * 16) = srcs[b][idx];
            }
        }
    }

    // ---- Gather phase: z = h[v] + sum_in h[u], split -> A_hi/A_lo smem ----
    {
        const float4* __restrict__ h4 = (const float4*)Hin;
        const int* __restrict__ csr = g_csr_src;
#pragma unroll 2
        for (int r = 0; r < 8; r++) {
            int srow = wid * 8 + r;
            int node = rowbase + srow;
            float4 acc = make_float4(0.f, 0.f, 0.f, 0.f);
            if (node < NN) {
                acc = h4[node * 32 + lane];
                int beg = __ldg(&g_rowstart[node]);
                int end = __ldg(&g_rowstart[node + 1]);
#pragma unroll 1
                for (int j = beg; j < end; j++) {
                    int s = __ldg(&csr[j]);
                    float4 v = h4[s * 32 + lane];
                    acc.x += v.x; acc.y += v.y; acc.z += v.z; acc.w += v.w;
                }
            }
            uint32_t h01, l01, h23, l23;
            split_pack(acc.x, acc.y, h01, l01);
            split_pack(acc.z, acc.w, h23, l23);
            uint32_t off = (uint32_t)srow * PITCH + lane * 8;
            *(uint32_t*)(smem + SM_AHI + off)     = h01;
            *(uint32_t*)(smem + SM_AHI + off + 4) = h23;
            *(uint32_t*)(smem + SM_ALO + off)     = l01;
            *(uint32_t*)(smem + SM_ALO + off + 4) = l23;
        }
    }
    __syncthreads();

    // ---- warp tiles / ldmatrix lane addressing (validated in R7) ----
    int warp_m = (wid >> 2) * 32;   // 0,32,64,96
    int warp_n = (wid & 3) * 32;    // 0,32,64,96
    int arow = ((lane >> 3) & 1) * 8 + (lane & 7);
    int acol = (lane >> 4) << 3;
    int brow = lane & 7;
    int bk = ((lane >> 3) & 1) * 8;
    uint32_t a_lane = (uint32_t)((warp_m + arow) * PITCH + acol * 2);
    uint32_t b_lane = (uint32_t)((warp_n + brow) * PITCH + bk * 2);

    float acc[2][4][4];

    // ---- GEMM1: hid = relu(z @ W1 + b1) ----
#pragma unroll
    for (int mi = 0; mi < 2; mi++)
#pragma unroll
        for (int nj = 0; nj < 4; nj++)
#pragma unroll
            for (int q = 0; q < 4; q++) acc[mi][nj][q] = 0.0f;

    gemm3pass(sbase + SM_AHI + a_lane, sbase + SM_ALO + a_lane,
              sbase + SM_W1HI + b_lane, sbase + SM_W1LO + b_lane, acc);

    __syncthreads();   // all warps done reading A before overwrite with hid

    // bias + relu + split, write hid into A_hi/A_lo smem
#pragma unroll
    for (int mi = 0; mi < 2; mi++) {
#pragma unroll
        for (int hh = 0; hh < 2; hh++) {
            int row = warp_m + mi * 16 + hh * 8 + (lane >> 2);
#pragma unroll
            for (int nj = 0; nj < 4; nj++) {
                int c = warp_n + nj * 8 + (lane & 3) * 2;
                float v0 = fmaxf(acc[mi][nj][hh * 2 + 0] + b1[c], 0.0f);
                float v1 = fmaxf(acc[mi][nj][hh * 2 + 1] + b1[c + 1], 0.0f);
                uint32_t hp, lp;
                split_pack(v0, v1, hp, lp);
                uint32_t off = (uint32_t)row * PITCH + c * 2;
                *(uint32_t*)(smem + SM_AHI + off) = hp;
                *(uint32_t*)(smem + SM_ALO + off) = lp;
            }
        }
    }
    __syncthreads();

    // ---- GEMM2: out = hid @ W2 + b2 (+relu unless last) ----
#pragma unroll
    for (int mi = 0; mi < 2; mi++)
#pragma unroll
        for (int nj = 0; nj < 4; nj++)
#pragma unroll
            for (int q = 0; q < 4; q++) acc[mi][nj][q] = 0.0f;

    gemm3pass(sbase + SM_AHI + a_lane, sbase + SM_ALO + a_lane,
              sbase + SM_W2HI + b_lane, sbase + SM_W2LO + b_lane, acc);

    // epilogue: bias + optional ReLU, fp32 store to global
#pragma unroll
    for (int mi = 0; mi < 2; mi++) {
#pragma unroll
        for (int hh = 0; hh < 2; hh++) {
            int gr = rowbase + warp_m + mi * 16 + hh * 8 + (lane >> 2);
            if (gr < outRows) {
#pragma unroll
                for (int nj = 0; nj < 4; nj++) {
                    int c = warp_n + nj * 8 + (lane & 3) * 2;
                    float v0 = acc[mi][nj][hh * 2 + 0] + b2[c];
                    float v1 = acc[mi][nj][hh * 2 + 1] + b2[c + 1];
                    if (doRelu2) { v0 = fmaxf(v0, 0.0f); v1 = fmaxf(v1, 0.0f); }
                    *(float2*)&Hout[(size_t)gr * DIM + c] = make_float2(v0, v1);
                }
            }
        }
    }
}

// ---------------------------------------------------------------------------
// Host launcher
// ---------------------------------------------------------------------------
extern "C" void kernel_launch(void* const* d_in, const int* in_sizes, int n_in,
                              void* d_out, int out_size) {
    const float* x   = (const float*)d_in[0];
    const int*   src = (const int*)  d_in[1];
    const int*   dst = (const int*)  d_in[2];
    const float* W1  = (const float*)d_in[3];
    const float* b1  = (const float*)d_in[4];
    const float* W2  = (const float*)d_in[5];
    const float* b2  = (const float*)d_in[6];
    float* out = (float*)d_out;

    float *ha, *hb;
    __nv_bfloat16 *w1hi, *w1lo, *w2hi, *w2lo;
    cudaGetSymbolAddress((void**)&ha,   g_ha);
    cudaGetSymbolAddress((void**)&hb,   g_hb);
    cudaGetSymbolAddress((void**)&w1hi, g_w1hi);
    cudaGetSymbolAddress((void**)&w1lo, g_w1lo);
    cudaGetSymbolAddress((void**)&w2hi, g_w2hi);
    cudaGetSymbolAddress((void**)&w2lo, g_w2lo);

    cudaFuncSetAttribute(fused_layer_kernel,
                         cudaFuncAttributeMaxDynamicSharedMemorySize, SMEM_DYN);

    // CSR build
    clear_counts_kernel<<<(NN + 255) / 256, 256>>>();
    hist_kernel<<<(NE + 255) / 256, 256>>>(dst);
    scan_kernel<<<1, 1024>>>();
    fill_kernel<<<(NE + 255) / 256, 256>>>(src, dst);

    // Weight splits (transposed, bf16 hi/lo)
    wprep_kernel<<<64, 256>>>(W1, w1hi, w1lo);
    wprep_kernel<<<64, 256>>>(W2, w2hi, w2lo);

    // Three fused layers
    fused_layer_kernel<<<NT, 512, SMEM_DYN>>>(x,  w1hi, w1lo, w2hi, w2lo, b1, b2, ha,  PADN, 1);
    fused_layer_kernel<<<NT, 512, SMEM_DYN>>>(ha, w1hi, w1lo, w2hi, w2lo, b1, b2, hb,  PADN, 1);
    fused_layer_kernel<<<NT, 512, SMEM_DYN>>>(hb, w1hi, w1lo, w2hi, w2lo, b1, b2, out, NN,   0);
}

// round 12
// speedup vs baseline: 2.1160x; 2.1160x over previous
#include <cuda_runtime.h>
#include <cuda_bf16.h>
#include <cstdint>
#include <cstddef>

// Problem constants
#define NN 100000
#define NE 600000
#define DIM 128
#define NT 782                     // ceil(NN/128)
#define PADN (NT * 128)            // 100096 padded rows
#define PFEATS (PADN * DIM)

// ---------------------------------------------------------------------------
// Device scratch (static — no runtime allocation; zero-initialized, pad rows
// of g_z are never written -> deterministic zeros)
// ---------------------------------------------------------------------------
__device__ __align__(16) float g_z[PFEATS];    // gather output
__device__ __align__(16) float g_ha[PFEATS];   // layer activations
__device__ __align__(16) float g_hb[PFEATS];
__device__ __nv_bfloat16 g_w1hi[DIM * DIM];    // W^T [n][k] bf16 hi
__device__ __nv_bfloat16 g_w1lo[DIM * DIM];
__device__ __nv_bfloat16 g_w2hi[DIM * DIM];
__device__ __nv_bfloat16 g_w2lo[DIM * DIM];
__device__ int g_deg[NN];
__device__ int g_cursor[NN];
__device__ int g_rowstart[NN + 1];
__device__ int g_csr_src[NE];

// ---------------------------------------------------------------------------
// CSR build (validated)
// ---------------------------------------------------------------------------
__global__ void clear_counts_kernel() {
    int i = blockIdx.x * blockDim.x + threadIdx.x;
    if (i < NN) { g_deg[i] = 0; g_cursor[i] = 0; }
}
__global__ void hist_kernel(const int* __restrict__ dst) {
    int e = blockIdx.x * blockDim.x + threadIdx.x;
    if (e < NE) atomicAdd(&g_deg[dst[e]], 1);
}
#define SCHUNK 98
__global__ void scan_kernel() {
    __shared__ int part[1024];
    int t = threadIdx.x;
    int start = t * SCHUNK;
    int end = min(start + SCHUNK, NN);
    int s = 0;
    for (int i = start; i < end; i++) s += g_deg[i];
    part[t] = s;
    __syncthreads();
    for (int off = 1; off < 1024; off <<= 1) {
        int v = (t >= off) ? part[t - off] : 0;
        __syncthreads();
        part[t] += v;
        __syncthreads();
    }
    int run = (t == 0) ? 0 : part[t - 1];
    for (int i = start; i < end; i++) { g_rowstart[i] = run; run += g_deg[i]; }
    if (t == 1023) g_rowstart[NN] = part[1023];
}
__global__ void fill_kernel(const int* __restrict__ src, const int* __restrict__ dst) {
    int e = blockIdx.x * blockDim.x + threadIdx.x;
    if (e < NE) {
        int v = dst[e];
        int pos = g_rowstart[v] + atomicAdd(&g_cursor[v], 1);
        g_csr_src[pos] = src[e];
    }
}

// ---------------------------------------------------------------------------
// Weight prep: W[k][n] fp32 -> W^T[n][k] bf16 hi/lo
// ---------------------------------------------------------------------------
__global__ void wprep_kernel(const float* __restrict__ W,
                             __nv_bfloat16* __restrict__ Hi,
                             __nv_bfloat16* __restrict__ Lo) {
    int idx = blockIdx.x * blockDim.x + threadIdx.x;
    if (idx >= DIM * DIM) return;
    int k = idx >> 7, n = idx & 127;
    float v = W[idx];
    __nv_bfloat16 h = __float2bfloat16(v);
    __nv_bfloat16 l = __float2bfloat16(v - __bfloat162float(h));
    Hi[n * DIM + k] = h;
    Lo[n * DIM + k] = l;
}

// ---------------------------------------------------------------------------
// Gather-sum (warp per node, high occupancy). Validated in rounds 4/7.
// ---------------------------------------------------------------------------
__global__ void gather_kernel(const float* __restrict__ h, float* __restrict__ z) {
    int warp = (blockIdx.x * blockDim.x + threadIdx.x) >> 5;
    int lane = threadIdx.x & 31;
    if (warp >= NN) return;
    const float4* __restrict__ h4 = (const float4*)h;
    float4 acc = h4[warp * 32 + lane];
    int beg = g_rowstart[warp];
    int end = g_rowstart[warp + 1];
    for (int j = beg; j < end; j++) {
        int s = g_csr_src[j];
        float4 v = h4[s * 32 + lane];
        acc.x += v.x; acc.y += v.y; acc.z += v.z; acc.w += v.w;
    }
    ((float4*)z)[warp * 32 + lane] = acc;
}

// ---------------------------------------------------------------------------
// mma.sync helpers (validated)
// ---------------------------------------------------------------------------
#define PITCH 272                          // padded smem row: 136 bf16 = 272 B
#define SM_AHI 0                           // A tile hi  (reused for hid hi)
#define SM_ALO (128 * PITCH)               // A tile lo  (reused for hid lo)
#define SM_W1HI (2 * 128 * PITCH)
#define SM_W1LO (3 * 128 * PITCH)
#define SM_W2HI (4 * 128 * PITCH)
#define SM_W2LO (5 * 128 * PITCH)
#define SMEM_DYN (6 * 128 * PITCH)         // 208896 B

static __device__ __forceinline__ uint32_t smem_u32(const void* p) {
    uint32_t a;
    asm("{ .reg .u64 t; cvta.to.shared.u64 t, %1; cvt.u32.u64 %0, t; }" : "=r"(a) : "l"(p));
    return a;
}
static __device__ __forceinline__ void ldm_x4(uint32_t* r, uint32_t addr) {
    asm volatile("ldmatrix.sync.aligned.m8n8.x4.shared.b16 {%0,%1,%2,%3}, [%4];"
                 : "=r"(r[0]), "=r"(r[1]), "=r"(r[2]), "=r"(r[3]) : "r"(addr));
}
static __device__ __forceinline__ void ldm_x2(uint32_t* r, uint32_t addr) {
    asm volatile("ldmatrix.sync.aligned.m8n8.x2.shared.b16 {%0,%1}, [%2];"
                 : "=r"(r[0]), "=r"(r[1]) : "r"(addr));
}
static __device__ __forceinline__ void mma_bf16(float* d, const uint32_t* a, const uint32_t* b) {
    asm volatile(
        "mma.sync.aligned.m16n8k16.row.col.f32.bf16.bf16.f32 "
        "{%0,%1,%2,%3}, {%4,%5,%6,%7}, {%8,%9}, {%0,%1,%2,%3};"
        : "+f"(d[0]), "+f"(d[1]), "+f"(d[2]), "+f"(d[3])
        : "r"(a[0]), "r"(a[1]), "r"(a[2]), "r"(a[3]), "r"(b[0]), "r"(b[1]));
}
static __device__ __forceinline__ void split_pack(float a, float b, uint32_t& hi, uint32_t& lo) {
    __nv_bfloat16 ha = __float2bfloat16(a), hb = __float2bfloat16(b);
    __nv_bfloat16 la = __float2bfloat16(a - __bfloat162float(ha));
    __nv_bfloat16 lb = __float2bfloat16(b - __bfloat162float(hb));
    __nv_bfloat162 H; H.x = ha; H.y = hb;
    __nv_bfloat162 L; L.x = la; L.y = lb;
    hi = *(uint32_t*)&H; lo = *(uint32_t*)&L;
}

// 3-pass split-fp32 GEMM core: warp tile 32(M) x 32(N), K=128.
// acc += A_hi*W_hi + A_hi*W_lo + A_lo*W_hi   (validated R10)
static __device__ __forceinline__ void gemm3pass(
    uint32_t sAhi, uint32_t sAlo, uint32_t sWhi, uint32_t sWlo,
    float acc[2][4][4]) {
#pragma unroll
    for (int pass = 0; pass < 3; pass++) {
        uint32_t sA = (pass == 2) ? sAlo : sAhi;
        uint32_t sW = (pass == 1) ? sWlo : sWhi;
#pragma unroll
        for (int k0 = 0; k0 < 128; k0 += 16) {
            uint32_t af[2][4], bf[4][2];
            ldm_x4(af[0], sA + k0 * 2);
            ldm_x4(af[1], sA + 16 * PITCH + k0 * 2);
#pragma unroll
            for (int nj = 0; nj < 4; nj++)
                ldm_x2(bf[nj], sW + nj * 8 * PITCH + k0 * 2);
#pragma unroll
            for (int mi = 0; mi < 2; mi++)
#pragma unroll
                for (int nj = 0; nj < 4; nj++)
                    mma_bf16(acc[mi][nj], af[mi], bf[nj]);
        }
    }
}

// ---------------------------------------------------------------------------
// Fused MLP kernel (NO gather): load z -> split -> GEMM1(+b1,ReLU) ->
// hid in smem -> GEMM2(+b2,opt ReLU) -> global. 512 threads, 1 CTA/tile.
// ---------------------------------------------------------------------------
__global__ void __launch_bounds__(512, 1)
mlp_pair_kernel(const float* __restrict__ Z,
                const __nv_bfloat16* __restrict__ W1h, const __nv_bfloat16* __restrict__ W1l,
                const __nv_bfloat16* __restrict__ W2h, const __nv_bfloat16* __restrict__ W2l,
                const float* __restrict__ b1, const float* __restrict__ b2,
                float* __restrict__ Hout, int outRows, int doRelu2) {
    extern __shared__ __align__(16) unsigned char smem[];
    uint32_t sbase = smem_u32(smem);
    int tid = threadIdx.x, wid = tid >> 5, lane = tid & 31;
    int rowbase = blockIdx.x * 128;

    // ---- Issue z-tile global loads FIRST (in flight during weight stores) ----
    const float4* Zg = (const float4*)(Z + (size_t)rowbase * DIM);
    float4 zreg[8];
#pragma unroll
    for (int i = 0; i < 8; i++) zreg[i] = Zg[tid + i * 512];

    // ---- Load weights (bf16 hi/lo, pre-transposed) into padded smem ----
    {
        const uint4* srcs[4] = {(const uint4*)W1h, (const uint4*)W1l,
                                (const uint4*)W2h, (const uint4*)W2l};
        const uint32_t offs[4] = {SM_W1HI, SM_W1LO, SM_W2HI, SM_W2LO};
#pragma unroll
        for (int b = 0; b < 4; b++) {
#pragma unroll
            for (int i = 0; i < 4; i++) {
                int idx = tid + i * 512;        // 2048 uint4 = 128x16
                int row = idx >> 4, c = idx & 15;
                *(uint4*)(smem + offs[b] + row * PITCH + c * 16) = srcs[b][idx];
            }
        }
    }

    // ---- Split z -> A_hi/A_lo smem ----
#pragma unroll
    for (int i = 0; i < 8; i++) {
        int idx = tid + i * 512;            // 4096 float4 = 128 rows x 32
        int row = idx >> 5, c4 = idx & 31;
        float4 v = zreg[i];
        uint32_t h01, l01, h23, l23;
        split_pack(v.x, v.y, h01, l01);
        split_pack(v.z, v.w, h23, l23);
        uint32_t off = (uint32_t)row * PITCH + c4 * 8;
        *(uint32_t*)(smem + SM_AHI + off)     = h01;
        *(uint32_t*)(smem + SM_AHI + off + 4) = h23;
        *(uint32_t*)(smem + SM_ALO + off)     = l01;
        *(uint32_t*)(smem + SM_ALO + off + 4) = l23;
    }
    __syncthreads();

    // ---- warp tiles / ldmatrix lane addressing (validated) ----
    int warp_m = (wid >> 2) * 32;   // 0,32,64,96
    int warp_n = (wid & 3) * 32;    // 0,32,64,96
    int arow = ((lane >> 3) & 1) * 8 + (lane & 7);
    int acol = (lane >> 4) << 3;
    int brow = lane & 7;
    int bk = ((lane >> 3) & 1) * 8;
    uint32_t a_lane = (uint32_t)((warp_m + arow) * PITCH + acol * 2);
    uint32_t b_lane = (uint32_t)((warp_n + brow) * PITCH + bk * 2);

    float acc[2][4][4];

    // ---- GEMM1: hid = relu(z @ W1 + b1) ----
#pragma unroll
    for (int mi = 0; mi < 2; mi++)
#pragma unroll
        for (int nj = 0; nj < 4; nj++)
#pragma unroll
            for (int q = 0; q < 4; q++) acc[mi][nj][q] = 0.0f;

    gemm3pass(sbase + SM_AHI + a_lane, sbase + SM_ALO + a_lane,
              sbase + SM_W1HI + b_lane, sbase + SM_W1LO + b_lane, acc);

    __syncthreads();   // all warps done reading A before overwrite with hid

    // bias + relu + split, write hid into A_hi/A_lo smem
#pragma unroll
    for (int mi = 0; mi < 2; mi++) {
#pragma unroll
        for (int hh = 0; hh < 2; hh++) {
            int row = warp_m + mi * 16 + hh * 8 + (lane >> 2);
#pragma unroll
            for (int nj = 0; nj < 4; nj++) {
                int c = warp_n + nj * 8 + (lane & 3) * 2;
                float v0 = fmaxf(acc[mi][nj][hh * 2 + 0] + b1[c], 0.0f);
                float v1 = fmaxf(acc[mi][nj][hh * 2 + 1] + b1[c + 1], 0.0f);
                uint32_t hp, lp;
                split_pack(v0, v1, hp, lp);
                uint32_t off = (uint32_t)row * PITCH + c * 2;
                *(uint32_t*)(smem + SM_AHI + off) = hp;
                *(uint32_t*)(smem + SM_ALO + off) = lp;
            }
        }
    }
    __syncthreads();

    // ---- GEMM2: out = hid @ W2 + b2 (+relu unless last) ----
#pragma unroll
    for (int mi = 0; mi < 2; mi++)
#pragma unroll
        for (int nj = 0; nj < 4; nj++)
#pragma unroll
            for (int q = 0; q < 4; q++) acc[mi][nj][q] = 0.0f;

    gemm3pass(sbase + SM_AHI + a_lane, sbase + SM_ALO + a_lane,
              sbase + SM_W2HI + b_lane, sbase + SM_W2LO + b_lane, acc);

    // epilogue: bias + optional ReLU, fp32 store to global
#pragma unroll
    for (int mi = 0; mi < 2; mi++) {
#pragma unroll
        for (int hh = 0; hh < 2; hh++) {
            int gr = rowbase + warp_m + mi * 16 + hh * 8 + (lane >> 2);
            if (gr < outRows) {
#pragma unroll
                for (int nj = 0; nj < 4; nj++) {
                    int c = warp_n + nj * 8 + (lane & 3) * 2;
                    float v0 = acc[mi][nj][hh * 2 + 0] + b2[c];
                    float v1 = acc[mi][nj][hh * 2 + 1] + b2[c + 1];
                    if (doRelu2) { v0 = fmaxf(v0, 0.0f); v1 = fmaxf(v1, 0.0f); }
                    *(float2*)&Hout[(size_t)gr * DIM + c] = make_float2(v0, v1);
                }
            }
        }
    }
}

// ---------------------------------------------------------------------------
// Host launcher
// ---------------------------------------------------------------------------
extern "C" void kernel_launch(void* const* d_in, const int* in_sizes, int n_in,
                              void* d_out, int out_size) {
    const float* x   = (const float*)d_in[0];
    const int*   src = (const int*)  d_in[1];
    const int*   dst = (const int*)  d_in[2];
    const float* W1  = (const float*)d_in[3];
    const float* b1  = (const float*)d_in[4];
    const float* W2  = (const float*)d_in[5];
    const float* b2  = (const float*)d_in[6];
    float* out = (float*)d_out;

    float *z, *ha, *hb;
    __nv_bfloat16 *w1hi, *w1lo, *w2hi, *w2lo;
    cudaGetSymbolAddress((void**)&z,    g_z);
    cudaGetSymbolAddress((void**)&ha,   g_ha);
    cudaGetSymbolAddress((void**)&hb,   g_hb);
    cudaGetSymbolAddress((void**)&w1hi, g_w1hi);
    cudaGetSymbolAddress((void**)&w1lo, g_w1lo);
    cudaGetSymbolAddress((void**)&w2hi, g_w2hi);
    cudaGetSymbolAddress((void**)&w2lo, g_w2lo);

    cudaFuncSetAttribute(mlp_pair_kernel,
                         cudaFuncAttributeMaxDynamicSharedMemorySize, SMEM_DYN);

    // CSR build
    clear_counts_kernel<<<(NN + 255) / 256, 256>>>();
    hist_kernel<<<(NE + 255) / 256, 256>>>(dst);
    scan_kernel<<<1, 1024>>>();
    fill_kernel<<<(NE + 255) / 256, 256>>>(src, dst);

    // Weight splits (transposed, bf16 hi/lo)
    wprep_kernel<<<64, 256>>>(W1, w1hi, w1lo);
    wprep_kernel<<<64, 256>>>(W2, w2hi, w2lo);

    const int gather_blocks = (NN * 32 + 255) / 256;

    // layer 1
    gather_kernel<<<gather_blocks, 256>>>(x, z);
    mlp_pair_kernel<<<NT, 512, SMEM_DYN>>>(z, w1hi, w1lo, w2hi, w2lo, b1, b2, ha, PADN, 1);
    // layer 2
    gather_kernel<<<gather_blocks, 256>>>(ha, z);
    mlp_pair_kernel<<<NT, 512, SMEM_DYN>>>(z, w1hi, w1lo, w2hi, w2lo, b1, b2, hb, PADN, 1);
    // layer 3 (no final ReLU)
    gather_kernel<<<gather_blocks, 256>>>(hb, z);
    mlp_pair_kernel<<<NT, 512, SMEM_DYN>>>(z, w1hi, w1lo, w2hi, w2lo, b1, b2, out, NN, 0);
}

// round 14
// speedup vs baseline: 2.2552x; 1.0658x over previous
#include <cuda_runtime.h>
#include <cuda_bf16.h>
#include <cstdint>
#include <cstddef>

// Problem constants
#define NN 100000
#define NE 600000
#define DIM 128
#define NT 782                     // ceil(NN/128)
#define PADN (NT * 128)            // 100096 padded rows
#define PFEATS (PADN * DIM)

// ---------------------------------------------------------------------------
// Device scratch (static — no runtime allocation; zero-initialized, pad rows
// of g_z are never written -> deterministic zeros)
// ---------------------------------------------------------------------------
__device__ __align__(16) float g_z[PFEATS];    // gather output
__device__ __align__(16) float g_ha[PFEATS];   // layer activations
__device__ __align__(16) float g_hb[PFEATS];
__device__ __nv_bfloat16 g_w1hi[DIM * DIM];    // W^T [n][k] bf16 hi
__device__ __nv_bfloat16 g_w1lo[DIM * DIM];
__device__ __nv_bfloat16 g_w2hi[DIM * DIM];
__device__ __nv_bfloat16 g_w2lo[DIM * DIM];
__device__ int g_deg[NN];
__device__ int g_cursor[NN];
__device__ int g_rowstart[NN + 1];
__device__ int g_csr_src[NE];

// ---------------------------------------------------------------------------
// CSR build (validated)
// ---------------------------------------------------------------------------
__global__ void clear_counts_kernel() {
    int i = blockIdx.x * blockDim.x + threadIdx.x;
    if (i < NN) { g_deg[i] = 0; g_cursor[i] = 0; }
}
__global__ void hist_kernel(const int* __restrict__ dst) {
    int e = blockIdx.x * blockDim.x + threadIdx.x;
    if (e < NE) atomicAdd(&g_deg[dst[e]], 1);
}
#define SCHUNK 98
__global__ void scan_kernel() {
    __shared__ int part[1024];
    int t = threadIdx.x;
    int start = t * SCHUNK;
    int end = min(start + SCHUNK, NN);
    int s = 0;
    for (int i = start; i < end; i++) s += g_deg[i];
    part[t] = s;
    __syncthreads();
    for (int off = 1; off < 1024; off <<= 1) {
        int v = (t >= off) ? part[t - off] : 0;
        __syncthreads();
        part[t] += v;
        __syncthreads();
    }
    int run = (t == 0) ? 0 : part[t - 1];
    for (int i = start; i < end; i++) { g_rowstart[i] = run; run += g_deg[i]; }
    if (t == 1023) g_rowstart[NN] = part[1023];
}
__global__ void fill_kernel(const int* __restrict__ src, const int* __restrict__ dst) {
    int e = blockIdx.x * blockDim.x + threadIdx.x;
    if (e < NE) {
        int v = dst[e];
        int pos = g_rowstart[v] + atomicAdd(&g_cursor[v], 1);
        g_csr_src[pos] = src[e];
    }
}

// ---------------------------------------------------------------------------
// Weight prep: W[k][n] fp32 -> W^T[n][k] bf16 hi/lo
// ---------------------------------------------------------------------------
__global__ void wprep_kernel(const float* __restrict__ W,
                             __nv_bfloat16* __restrict__ Hi,
                             __nv_bfloat16* __restrict__ Lo) {
    int idx = blockIdx.x * blockDim.x + threadIdx.x;
    if (idx >= DIM * DIM) return;
    int k = idx >> 7, n = idx & 127;
    float v = W[idx];
    __nv_bfloat16 h = __float2bfloat16(v);
    __nv_bfloat16 l = __float2bfloat16(v - __bfloat162float(h));
    Hi[n * DIM + k] = h;
    Lo[n * DIM + k] = l;
}

// ---------------------------------------------------------------------------
// Gather-sum (warp per node, high occupancy). Validated.
// ---------------------------------------------------------------------------
__global__ void gather_kernel(const float* __restrict__ h, float* __restrict__ z) {
    int warp = (blockIdx.x * blockDim.x + threadIdx.x) >> 5;
    int lane = threadIdx.x & 31;
    if (warp >= NN) return;
    const float4* __restrict__ h4 = (const float4*)h;
    float4 acc = h4[warp * 32 + lane];
    int beg = g_rowstart[warp];
    int end = g_rowstart[warp + 1];
    for (int j = beg; j < end; j++) {
        int s = g_csr_src[j];
        float4 v = h4[s * 32 + lane];
        acc.x += v.x; acc.y += v.y; acc.z += v.z; acc.w += v.w;
    }
    ((float4*)z)[warp * 32 + lane] = acc;
}

// ---------------------------------------------------------------------------
// mma.sync helpers (validated)
// ---------------------------------------------------------------------------
#define PITCH 272                          // padded smem row: 136 bf16 = 272 B
#define SM_AHI 0                           // A tile hi  (reused for hid hi)
#define SM_ALO (128 * PITCH)               // A tile lo  (reused for hid lo)
#define SM_W1HI (2 * 128 * PITCH)
#define SM_W1LO (3 * 128 * PITCH)
#define SM_W2HI (4 * 128 * PITCH)
#define SM_W2LO (5 * 128 * PITCH)
#define SMEM_DYN (6 * 128 * PITCH)         // 208896 B

static __device__ __forceinline__ uint32_t smem_u32(const void* p) {
    uint32_t a;
    asm("{ .reg .u64 t; cvta.to.shared.u64 t, %1; cvt.u32.u64 %0, t; }" : "=r"(a) : "l"(p));
    return a;
}
static __device__ __forceinline__ void ldm_x4(uint32_t* r, uint32_t addr) {
    asm volatile("ldmatrix.sync.aligned.m8n8.x4.shared.b16 {%0,%1,%2,%3}, [%4];"
                 : "=r"(r[0]), "=r"(r[1]), "=r"(r[2]), "=r"(r[3]) : "r"(addr));
}
static __device__ __forceinline__ void ldm_x2(uint32_t* r, uint32_t addr) {
    asm volatile("ldmatrix.sync.aligned.m8n8.x2.shared.b16 {%0,%1}, [%2];"
                 : "=r"(r[0]), "=r"(r[1]) : "r"(addr));
}
static __device__ __forceinline__ void mma_bf16(float* d, const uint32_t* a, const uint32_t* b) {
    asm volatile(
        "mma.sync.aligned.m16n8k16.row.col.f32.bf16.bf16.f32 "
        "{%0,%1,%2,%3}, {%4,%5,%6,%7}, {%8,%9}, {%0,%1,%2,%3};"
        : "+f"(d[0]), "+f"(d[1]), "+f"(d[2]), "+f"(d[3])
        : "r"(a[0]), "r"(a[1]), "r"(a[2]), "r"(a[3]), "r"(b[0]), "r"(b[1]));
}
static __device__ __forceinline__ void split_pack(float a, float b, uint32_t& hi, uint32_t& lo) {
    __nv_bfloat16 ha = __float2bfloat16(a), hb = __float2bfloat16(b);
    __nv_bfloat16 la = __float2bfloat16(a - __bfloat162float(ha));
    __nv_bfloat16 lb = __float2bfloat16(b - __bfloat162float(hb));
    __nv_bfloat162 H; H.x = ha; H.y = hb;
    __nv_bfloat162 L; L.x = la; L.y = lb;
    hi = *(uint32_t*)&H; lo = *(uint32_t*)&L;
}

// Fused 3-pass split-fp32 GEMM core: warp tile 32(M) x 32(N), K=128.
// Per k-step: load A_hi/A_lo/W_hi/W_lo fragments ONCE (12 LDSM), then issue
// all 24 HMMA: acc += A_hi*W_hi + A_hi*W_lo + A_lo*W_hi.
// Same additions as the 3-sequential-pass version, reordered (fp32 accum).
static __device__ __forceinline__ void gemm3fused(
    uint32_t sAhi, uint32_t sAlo, uint32_t sWhi, uint32_t sWlo,
    float acc[2][4][4]) {
#pragma unroll
    for (int k0 = 0; k0 < 128; k0 += 16) {
        uint32_t ah[2][4], al[2][4], wh[4][2], wl[4][2];
        ldm_x4(ah[0], sAhi + k0 * 2);
        ldm_x4(ah[1], sAhi + 16 * PITCH + k0 * 2);
        ldm_x4(al[0], sAlo + k0 * 2);
        ldm_x4(al[1], sAlo + 16 * PITCH + k0 * 2);
#pragma unroll
        for (int nj = 0; nj < 4; nj++) {
            ldm_x2(wh[nj], sWhi + nj * 8 * PITCH + k0 * 2);
            ldm_x2(wl[nj], sWlo + nj * 8 * PITCH + k0 * 2);
        }
#pragma unroll
        for (int mi = 0; mi < 2; mi++)
#pragma unroll
            for (int nj = 0; nj < 4; nj++) {
                mma_bf16(acc[mi][nj], ah[mi], wh[nj]);
                mma_bf16(acc[mi][nj], ah[mi], wl[nj]);
                mma_bf16(acc[mi][nj], al[mi], wh[nj]);
            }
    }
}

// ---------------------------------------------------------------------------
// Fused MLP kernel (NO gather): load z -> split -> GEMM1(+b1,ReLU) ->
// hid in smem -> GEMM2(+b2,opt ReLU) -> global. 512 threads, 1 CTA/tile.
// ---------------------------------------------------------------------------
__global__ void __launch_bounds__(512, 1)
mlp_pair_kernel(const float* __restrict__ Z,
                const __nv_bfloat16* __restrict__ W1h, const __nv_bfloat16* __restrict__ W1l,
                const __nv_bfloat16* __restrict__ W2h, const __nv_bfloat16* __restrict__ W2l,
                const float* __restrict__ b1, const float* __restrict__ b2,
                float* __restrict__ Hout, int outRows, int doRelu2) {
    extern __shared__ __align__(16) unsigned char smem[];
    uint32_t sbase = smem_u32(smem);
    int tid = threadIdx.x, wid = tid >> 5, lane = tid & 31;
    int rowbase = blockIdx.x * 128;

    // ---- Issue z-tile global loads FIRST (in flight during weight stores) ----
    const float4* Zg = (const float4*)(Z + (size_t)rowbase * DIM);
    float4 zreg[8];
#pragma unroll
    for (int i = 0; i < 8; i++) zreg[i] = Zg[tid + i * 512];

    // ---- Load weights (bf16 hi/lo, pre-transposed) into padded smem ----
    {
        const uint4* srcs[4] = {(const uint4*)W1h, (const uint4*)W1l,
                                (const uint4*)W2h, (const uint4*)W2l};
        const uint32_t offs[4] = {SM_W1HI, SM_W1LO, SM_W2HI, SM_W2LO};
#pragma unroll
        for (int b = 0; b < 4; b++) {
#pragma unroll
            for (int i = 0; i < 4; i++) {
                int idx = tid + i * 512;        // 2048 uint4 = 128x16
                int row = idx >> 4, c = idx & 15;
                *(uint4*)(smem + offs[b] + row * PITCH + c * 16) = srcs[b][idx];
            }
        }
    }

    // ---- Split z -> A_hi/A_lo smem ----
#pragma unroll
    for (int i = 0; i < 8; i++) {
        int idx = tid + i * 512;            // 4096 float4 = 128 rows x 32
        int row = idx >> 5, c4 = idx & 31;
        float4 v = zreg[i];
        uint32_t h01, l01, h23, l23;
        split_pack(v.x, v.y, h01, l01);
        split_pack(v.z, v.w, h23, l23);
        uint32_t off = (uint32_t)row * PITCH + c4 * 8;
        *(uint32_t*)(smem + SM_AHI + off)     = h01;
        *(uint32_t*)(smem + SM_AHI + off + 4) = h23;
        *(uint32_t*)(smem + SM_ALO + off)     = l01;
        *(uint32_t*)(smem + SM_ALO + off + 4) = l23;
    }
    __syncthreads();

    // ---- warp tiles / ldmatrix lane addressing (validated) ----
    int warp_m = (wid >> 2) * 32;   // 0,32,64,96
    int warp_n = (wid & 3) * 32;    // 0,32,64,96
    int arow = ((lane >> 3) & 1) * 8 + (lane & 7);
    int acol = (lane >> 4) << 3;
    int brow = lane & 7;
    int bk = ((lane >> 3) & 1) * 8;
    uint32_t a_lane = (uint32_t)((warp_m + arow) * PITCH + acol * 2);
    uint32_t b_lane = (uint32_t)((warp_n + brow) * PITCH + bk * 2);

    float acc[2][4][4];

    // ---- GEMM1: hid = relu(z @ W1 + b1) ----
#pragma unroll
    for (int mi = 0; mi < 2; mi++)
#pragma unroll
        for (int nj = 0; nj < 4; nj++)
#pragma unroll
            for (int q = 0; q < 4; q++) acc[mi][nj][q] = 0.0f;

    gemm3fused(sbase + SM_AHI + a_lane, sbase + SM_ALO + a_lane,
               sbase + SM_W1HI + b_lane, sbase + SM_W1LO + b_lane, acc);

    __syncthreads();   // all warps done reading A before overwrite with hid

    // bias + relu + split, write hid into A_hi/A_lo smem
#pragma unroll
    for (int mi = 0; mi < 2; mi++) {
#pragma unroll
        for (int hh = 0; hh < 2; hh++) {
            int row = warp_m + mi * 16 + hh * 8 + (lane >> 2);
#pragma unroll
            for (int nj = 0; nj < 4; nj++) {
                int c = warp_n + nj * 8 + (lane & 3) * 2;
                float v0 = fmaxf(acc[mi][nj][hh * 2 + 0] + b1[c], 0.0f);
                float v1 = fmaxf(acc[mi][nj][hh * 2 + 1] + b1[c + 1], 0.0f);
                uint32_t hp, lp;
                split_pack(v0, v1, hp, lp);
                uint32_t off = (uint32_t)row * PITCH + c * 2;
                *(uint32_t*)(smem + SM_AHI + off) = hp;
                *(uint32_t*)(smem + SM_ALO + off) = lp;
            }
        }
    }
    __syncthreads();

    // ---- GEMM2: out = hid @ W2 + b2 (+relu unless last) ----
#pragma unroll
    for (int mi = 0; mi < 2; mi++)
#pragma unroll
        for (int nj = 0; nj < 4; nj++)
#pragma unroll
            for (int q = 0; q < 4; q++) acc[mi][nj][q] = 0.0f;

    gemm3fused(sbase + SM_AHI + a_lane, sbase + SM_ALO + a_lane,
               sbase + SM_W2HI + b_lane, sbase + SM_W2LO + b_lane, acc);

    // epilogue: bias + optional ReLU, fp32 store to global
#pragma unroll
    for (int mi = 0; mi < 2; mi++) {
#pragma unroll
        for (int hh = 0; hh < 2; hh++) {
            int gr = rowbase + warp_m + mi * 16 + hh * 8 + (lane >> 2);
            if (gr < outRows) {
#pragma unroll
                for (int nj = 0; nj < 4; nj++) {
                    int c = warp_n + nj * 8 + (lane & 3) * 2;
                    float v0 = acc[mi][nj][hh * 2 + 0] + b2[c];
                    float v1 = acc[mi][nj][hh * 2 + 1] + b2[c + 1];
                    if (doRelu2) { v0 = fmaxf(v0, 0.0f); v1 = fmaxf(v1, 0.0f); }
                    *(float2*)&Hout[(size_t)gr * DIM + c] = make_float2(v0, v1);
                }
            }
        }
    }
}

// ---------------------------------------------------------------------------
// Host launcher
// ---------------------------------------------------------------------------
extern "C" void kernel_launch(void* const* d_in, const int* in_sizes, int n_in,
                              void* d_out, int out_size) {
    const float* x   = (const float*)d_in[0];
    const int*   src = (const int*)  d_in[1];
    const int*   dst = (const int*)  d_in[2];
    const float* W1  = (const float*)d_in[3];
    const float* b1  = (const float*)d_in[4];
    const float* W2  = (const float*)d_in[5];
    const float* b2  = (const float*)d_in[6];
    float* out = (float*)d_out;

    float *z, *ha, *hb;
    __nv_bfloat16 *w1hi, *w1lo, *w2hi, *w2lo;
    cudaGetSymbolAddress((void**)&z,    g_z);
    cudaGetSymbolAddress((void**)&ha,   g_ha);
    cudaGetSymbolAddress((void**)&hb,   g_hb);
    cudaGetSymbolAddress((void**)&w1hi, g_w1hi);
    cudaGetSymbolAddress((void**)&w1lo, g_w1lo);
    cudaGetSymbolAddress((void**)&w2hi, g_w2hi);
    cudaGetSymbolAddress((void**)&w2lo, g_w2lo);

    cudaFuncSetAttribute(mlp_pair_kernel,
                         cudaFuncAttributeMaxDynamicSharedMemorySize, SMEM_DYN);

    // CSR build
    clear_counts_kernel<<<(NN + 255) / 256, 256>>>();
    hist_kernel<<<(NE + 255) / 256, 256>>>(dst);
    scan_kernel<<<1, 1024>>>();
    fill_kernel<<<(NE + 255) / 256, 256>>>(src, dst);

    // Weight splits (transposed, bf16 hi/lo)
    wprep_kernel<<<64, 256>>>(W1, w1hi, w1lo);
    wprep_kernel<<<64, 256>>>(W2, w2hi, w2lo);

    const int gather_blocks = (NN * 32 + 255) / 256;

    // layer 1
    gather_kernel<<<gather_blocks, 256>>>(x, z);
    mlp_pair_kernel<<<NT, 512, SMEM_DYN>>>(z, w1hi, w1lo, w2hi, w2lo, b1, b2, ha, PADN, 1);
    // layer 2
    gather_kernel<<<gather_blocks, 256>>>(ha, z);
    mlp_pair_kernel<<<NT, 512, SMEM_DYN>>>(z, w1hi, w1lo, w2hi, w2lo, b1, b2, hb, PADN, 1);
    // layer 3 (no final ReLU)
    gather_kernel<<<gather_blocks, 256>>>(hb, z);
    mlp_pair_kernel<<<NT, 512, SMEM_DYN>>>(z, w1hi, w1lo, w2hi, w2lo, b1, b2, out, NN, 0);
}

// round 15
// speedup vs baseline: 2.2712x; 1.0071x over previous
#include <cuda_runtime.h>
#include <cuda_bf16.h>
#include <cstdint>
#include <cstddef>

// Problem constants
#define NN 100000
#define NE 600000
#define DIM 128
#define NT 782                     // ceil(NN/128)
#define PADN (NT * 128)            // 100096 padded rows
#define PFEATS (PADN * DIM)

// ---------------------------------------------------------------------------
// Device scratch (static — no runtime allocation; zero-initialized, pad rows
// of g_z are never written -> deterministic zeros)
// ---------------------------------------------------------------------------
__device__ __align__(16) float g_z[PFEATS];    // gather output
__device__ __align__(16) float g_ha[PFEATS];   // layer activations
__device__ __align__(16) float g_hb[PFEATS];
__device__ __nv_bfloat16 g_w1hi[DIM * DIM];    // W^T [n][k] bf16 hi
__device__ __nv_bfloat16 g_w1lo[DIM * DIM];
__device__ __nv_bfloat16 g_w2hi[DIM * DIM];
__device__ __nv_bfloat16 g_w2lo[DIM * DIM];
__device__ int g_deg[NN];
__device__ int g_cursor[NN];
__device__ int g_rowstart[NN + 1];
__device__ int g_csr_src[NE];

// ---------------------------------------------------------------------------
// CSR build (validated)
// ---------------------------------------------------------------------------
__global__ void clear_counts_kernel() {
    int i = blockIdx.x * blockDim.x + threadIdx.x;
    if (i < NN) { g_deg[i] = 0; g_cursor[i] = 0; }
}
__global__ void hist_kernel(const int* __restrict__ dst) {
    int e = blockIdx.x * blockDim.x + threadIdx.x;
    if (e < NE) atomicAdd(&g_deg[dst[e]], 1);
}
#define SCHUNK 98
__global__ void scan_kernel() {
    __shared__ int part[1024];
    int t = threadIdx.x;
    int start = t * SCHUNK;
    int end = min(start + SCHUNK, NN);
    int s = 0;
    for (int i = start; i < end; i++) s += g_deg[i];
    part[t] = s;
    __syncthreads();
    for (int off = 1; off < 1024; off <<= 1) {
        int v = (t >= off) ? part[t - off] : 0;
        __syncthreads();
        part[t] += v;
        __syncthreads();
    }
    int run = (t == 0) ? 0 : part[t - 1];
    for (int i = start; i < end; i++) { g_rowstart[i] = run; run += g_deg[i]; }
    if (t == 1023) g_rowstart[NN] = part[1023];
}
__global__ void fill_kernel(const int* __restrict__ src, const int* __restrict__ dst) {
    int e = blockIdx.x * blockDim.x + threadIdx.x;
    if (e < NE) {
        int v = dst[e];
        int pos = g_rowstart[v] + atomicAdd(&g_cursor[v], 1);
        g_csr_src[pos] = src[e];
    }
}

// ---------------------------------------------------------------------------
// Weight prep: W[k][n] fp32 -> W^T[n][k] bf16 hi/lo
// ---------------------------------------------------------------------------
__global__ void wprep_kernel(const float* __restrict__ W,
                             __nv_bfloat16* __restrict__ Hi,
                             __nv_bfloat16* __restrict__ Lo) {
    int idx = blockIdx.x * blockDim.x + threadIdx.x;
    if (idx >= DIM * DIM) return;
    int k = idx >> 7, n = idx & 127;
    float v = W[idx];
    __nv_bfloat16 h = __float2bfloat16(v);
    __nv_bfloat16 l = __float2bfloat16(v - __bfloat162float(h));
    Hi[n * DIM + k] = h;
    Lo[n * DIM + k] = l;
}

// ---------------------------------------------------------------------------
// Gather-sum (warp per node, high occupancy). Validated.
// ---------------------------------------------------------------------------
__global__ void gather_kernel(const float* __restrict__ h, float* __restrict__ z) {
    int warp = (blockIdx.x * blockDim.x + threadIdx.x) >> 5;
    int lane = threadIdx.x & 31;
    if (warp >= NN) return;
    const float4* __restrict__ h4 = (const float4*)h;
    float4 acc = h4[warp * 32 + lane];
    int beg = g_rowstart[warp];
    int end = g_rowstart[warp + 1];
    for (int j = beg; j < end; j++) {
        int s = g_csr_src[j];
        float4 v = h4[s * 32 + lane];
        acc.x += v.x; acc.y += v.y; acc.z += v.z; acc.w += v.w;
    }
    ((float4*)z)[warp * 32 + lane] = acc;
}

// ---------------------------------------------------------------------------
// mma.sync helpers (validated)
// ---------------------------------------------------------------------------
#define PITCH 272                          // padded smem row: 136 bf16 = 272 B
#define SM_AHI 0                           // A tile hi  (reused for hid hi)
#define SM_ALO (128 * PITCH)               // A tile lo  (reused for hid lo)
#define SM_W1HI (2 * 128 * PITCH)
#define SM_W1LO (3 * 128 * PITCH)
#define SM_W2HI (4 * 128 * PITCH)
#define SM_W2LO (5 * 128 * PITCH)
#define SMEM_DYN (6 * 128 * PITCH)         // 208896 B

static __device__ __forceinline__ uint32_t smem_u32(const void* p) {
    uint32_t a;
    asm("{ .reg .u64 t; cvta.to.shared.u64 t, %1; cvt.u32.u64 %0, t; }" : "=r"(a) : "l"(p));
    return a;
}
static __device__ __forceinline__ void ldm_x4(uint32_t* r, uint32_t addr) {
    asm volatile("ldmatrix.sync.aligned.m8n8.x4.shared.b16 {%0,%1,%2,%3}, [%4];"
                 : "=r"(r[0]), "=r"(r[1]), "=r"(r[2]), "=r"(r[3]) : "r"(addr));
}
static __device__ __forceinline__ void mma_bf16(float* d, const uint32_t* a, const uint32_t* b) {
    asm volatile(
        "mma.sync.aligned.m16n8k16.row.col.f32.bf16.bf16.f32 "
        "{%0,%1,%2,%3}, {%4,%5,%6,%7}, {%8,%9}, {%0,%1,%2,%3};"
        : "+f"(d[0]), "+f"(d[1]), "+f"(d[2]), "+f"(d[3])
        : "r"(a[0]), "r"(a[1]), "r"(a[2]), "r"(a[3]), "r"(b[0]), "r"(b[1]));
}
static __device__ __forceinline__ void split_pack(float a, float b, uint32_t& hi, uint32_t& lo) {
    __nv_bfloat16 ha = __float2bfloat16(a), hb = __float2bfloat16(b);
    __nv_bfloat16 la = __float2bfloat16(a - __bfloat162float(ha));
    __nv_bfloat16 lb = __float2bfloat16(b - __bfloat162float(hb));
    __nv_bfloat162 H; H.x = ha; H.y = hb;
    __nv_bfloat162 L; L.x = la; L.y = lb;
    hi = *(uint32_t*)&H; lo = *(uint32_t*)&L;
}

// Fused 3-term split-fp32 GEMM core: warp tile 32(M) x 32(N), K=128.
// Per k-step: 8 LDSM.x4 total (4 A + 4 W via paired-nj x4), then 24 HMMA
// issued TERM-MAJOR (8 independent accumulators per term group):
//   acc += A_hi*W_hi;  acc += A_hi*W_lo;  acc += A_lo*W_hi
// sA* addressed with a_lane (x4 A fragment layout, validated R7).
// sW* addressed with b_lane4:
//   row = warp_n + ((lane>>4)&1)*8 + (lane&7), colbyte = ((lane>>3)&1)*16
// so one x4 returns {nj, nj}-klo/khi and {nj+1}-klo/khi fragments.
static __device__ __forceinline__ void gemm3fused(
    uint32_t sAhi, uint32_t sAlo, uint32_t sWhi, uint32_t sWlo,
    float acc[2][4][4]) {
#pragma unroll
    for (int k0 = 0; k0 < 128; k0 += 16) {
        uint32_t ah[2][4], al[2][4], wh[4][2], wl[4][2];
        ldm_x4(ah[0], sAhi + k0 * 2);
        ldm_x4(ah[1], sAhi + 16 * PITCH + k0 * 2);
        ldm_x4(al[0], sAlo + k0 * 2);
        ldm_x4(al[1], sAlo + 16 * PITCH + k0 * 2);
#pragma unroll
        for (int njp = 0; njp < 2; njp++) {
            uint32_t t[4];
            ldm_x4(t, sWhi + njp * 16 * PITCH + k0 * 2);
            wh[2 * njp + 0][0] = t[0]; wh[2 * njp + 0][1] = t[1];
            wh[2 * njp + 1][0] = t[2]; wh[2 * njp + 1][1] = t[3];
            ldm_x4(t, sWlo + njp * 16 * PITCH + k0 * 2);
            wl[2 * njp + 0][0] = t[0]; wl[2 * njp + 0][1] = t[1];
            wl[2 * njp + 1][0] = t[2]; wl[2 * njp + 1][1] = t[3];
        }
        // term-major: 8 independent acc quads between dependent reuses
#pragma unroll
        for (int mi = 0; mi < 2; mi++)
#pragma unroll
            for (int nj = 0; nj < 4; nj++)
                mma_bf16(acc[mi][nj], ah[mi], wh[nj]);
#pragma unroll
        for (int mi = 0; mi < 2; mi++)
#pragma unroll
            for (int nj = 0; nj < 4; nj++)
                mma_bf16(acc[mi][nj], ah[mi], wl[nj]);
#pragma unroll
        for (int mi = 0; mi < 2; mi++)
#pragma unroll
            for (int nj = 0; nj < 4; nj++)
                mma_bf16(acc[mi][nj], al[mi], wh[nj]);
    }
}

// ---------------------------------------------------------------------------
// Fused MLP kernel (NO gather): load z -> split -> GEMM1(+b1,ReLU) ->
// hid in smem -> GEMM2(+b2,opt ReLU) -> global. 512 threads, 1 CTA/tile.
// ---------------------------------------------------------------------------
__global__ void __launch_bounds__(512, 1)
mlp_pair_kernel(const float* __restrict__ Z,
                const __nv_bfloat16* __restrict__ W1h, const __nv_bfloat16* __restrict__ W1l,
                const __nv_bfloat16* __restrict__ W2h, const __nv_bfloat16* __restrict__ W2l,
                const float* __restrict__ b1, const float* __restrict__ b2,
                float* __restrict__ Hout, int outRows, int doRelu2) {
    extern __shared__ __align__(16) unsigned char smem[];
    uint32_t sbase = smem_u32(smem);
    int tid = threadIdx.x, wid = tid >> 5, lane = tid & 31;
    int rowbase = blockIdx.x * 128;

    // ---- Issue z-tile global loads FIRST (in flight during weight stores) ----
    const float4* Zg = (const float4*)(Z + (size_t)rowbase * DIM);
    float4 zreg[8];
#pragma unroll
    for (int i = 0; i < 8; i++) zreg[i] = Zg[tid + i * 512];

    // ---- Load weights (bf16 hi/lo, pre-transposed) into padded smem ----
    {
        const uint4* srcs[4] = {(const uint4*)W1h, (const uint4*)W1l,
                                (const uint4*)W2h, (const uint4*)W2l};
        const uint32_t offs[4] = {SM_W1HI, SM_W1LO, SM_W2HI, SM_W2LO};
#pragma unroll
        for (int b = 0; b < 4; b++) {
#pragma unroll
            for (int i = 0; i < 4; i++) {
                int idx = tid + i * 512;        // 2048 uint4 = 128x16
                int row = idx >> 4, c = idx & 15;
                *(uint4*)(smem + offs[b] + row * PITCH + c * 16) = srcs[b][idx];
            }
        }
    }

    // ---- Split z -> A_hi/A_lo smem ----
#pragma unroll
    for (int i = 0; i < 8; i++) {
        int idx = tid + i * 512;            // 4096 float4 = 128 rows x 32
        int row = idx >> 5, c4 = idx & 31;
        float4 v = zreg[i];
        uint32_t h01, l01, h23, l23;
        split_pack(v.x, v.y, h01, l01);
        split_pack(v.z, v.w, h23, l23);
        uint32_t off = (uint32_t)row * PITCH + c4 * 8;
        *(uint32_t*)(smem + SM_AHI + off)     = h01;
        *(uint32_t*)(smem + SM_AHI + off + 4) = h23;
        *(uint32_t*)(smem + SM_ALO + off)     = l01;
        *(uint32_t*)(smem + SM_ALO + off + 4) = l23;
    }
    __syncthreads();

    // ---- warp tiles / ldmatrix lane addressing ----
    int warp_m = (wid >> 2) * 32;   // 0,32,64,96
    int warp_n = (wid & 3) * 32;    // 0,32,64,96
    // A (validated R7): x4 fragment layout
    int arow = ((lane >> 3) & 1) * 8 + (lane & 7);
    int acol = (lane >> 4) << 3;
    uint32_t a_lane = (uint32_t)((warp_m + arow) * PITCH + acol * 2);
    // W x4 (paired nj): lanes 0-7 rows nj+0..7 klo, 8-15 khi, 16-23 rows +8 klo, 24-31 khi
    int brow4 = ((lane >> 4) & 1) * 8 + (lane & 7);
    int bk4 = ((lane >> 3) & 1) * 16;   // byte offset of k-half
    uint32_t b_lane4 = (uint32_t)((warp_n + brow4) * PITCH + bk4);

    float acc[2][4][4];

    // ---- GEMM1: hid = relu(z @ W1 + b1) ----
#pragma unroll
    for (int mi = 0; mi < 2; mi++)
#pragma unroll
        for (int nj = 0; nj < 4; nj++)
#pragma unroll
            for (int q = 0; q < 4; q++) acc[mi][nj][q] = 0.0f;

    gemm3fused(sbase + SM_AHI + a_lane, sbase + SM_ALO + a_lane,
               sbase + SM_W1HI + b_lane4, sbase + SM_W1LO + b_lane4, acc);

    __syncthreads();   // all warps done reading A before overwrite with hid

    // bias + relu + split, write hid into A_hi/A_lo smem
#pragma unroll
    for (int mi = 0; mi < 2; mi++) {
#pragma unroll
        for (int hh = 0; hh < 2; hh++) {
            int row = warp_m + mi * 16 + hh * 8 + (lane >> 2);
#pragma unroll
            for (int nj = 0; nj < 4; nj++) {
                int c = warp_n + nj * 8 + (lane & 3) * 2;
                float v0 = fmaxf(acc[mi][nj][hh * 2 + 0] + b1[c], 0.0f);
                float v1 = fmaxf(acc[mi][nj][hh * 2 + 1] + b1[c + 1], 0.0f);
                uint32_t hp, lp;
                split_pack(v0, v1, hp, lp);
                uint32_t off = (uint32_t)row * PITCH + c * 2;
                *(uint32_t*)(smem + SM_AHI + off) = hp;
                *(uint32_t*)(smem + SM_ALO + off) = lp;
            }
        }
    }
    __syncthreads();

    // ---- GEMM2: out = hid @ W2 + b2 (+relu unless last) ----
#pragma unroll
    for (int mi = 0; mi < 2; mi++)
#pragma unroll
        for (int nj = 0; nj < 4; nj++)
#pragma unroll
            for (int q = 0; q < 4; q++) acc[mi][nj][q] = 0.0f;

    gemm3fused(sbase + SM_AHI + a_lane, sbase + SM_ALO + a_lane,
               sbase + SM_W2HI + b_lane4, sbase + SM_W2LO + b_lane4, acc);

    // epilogue: bias + optional ReLU, fp32 store to global
#pragma unroll
    for (int mi = 0; mi < 2; mi++) {
#pragma unroll
        for (int hh = 0; hh < 2; hh++) {
            int gr = rowbase + warp_m + mi * 16 + hh * 8 + (lane >> 2);
            if (gr < outRows) {
#pragma unroll
                for (int nj = 0; nj < 4; nj++) {
                    int c = warp_n + nj * 8 + (lane & 3) * 2;
                    float v0 = acc[mi][nj][hh * 2 + 0] + b2[c];
                    float v1 = acc[mi][nj][hh * 2 + 1] + b2[c + 1];
                    if (doRelu2) { v0 = fmaxf(v0, 0.0f); v1 = fmaxf(v1, 0.0f); }
                    *(float2*)&Hout[(size_t)gr * DIM + c] = make_float2(v0, v1);
                }
            }
        }
    }
}

// ---------------------------------------------------------------------------
// Host launcher
// ---------------------------------------------------------------------------
extern "C" void kernel_launch(void* const* d_in, const int* in_sizes, int n_in,
                              void* d_out, int out_size) {
    const float* x   = (const float*)d_in[0];
    const int*   src = (const int*)  d_in[1];
    const int*   dst = (const int*)  d_in[2];
    const float* W1  = (const float*)d_in[3];
    const float* b1  = (const float*)d_in[4];
    const float* W2  = (const float*)d_in[5];
    const float* b2  = (const float*)d_in[6];
    float* out = (float*)d_out;

    float *z, *ha, *hb;
    __nv_bfloat16 *w1hi, *w1lo, *w2hi, *w2lo;
    cudaGetSymbolAddress((void**)&z,    g_z);
    cudaGetSymbolAddress((void**)&ha,   g_ha);
    cudaGetSymbolAddress((void**)&hb,   g_hb);
    cudaGetSymbolAddress((void**)&w1hi, g_w1hi);
    cudaGetSymbolAddress((void**)&w1lo, g_w1lo);
    cudaGetSymbolAddress((void**)&w2hi, g_w2hi);
    cudaGetSymbolAddress((void**)&w2lo, g_w2lo);

    cudaFuncSetAttribute(mlp_pair_kernel,
                         cudaFuncAttributeMaxDynamicSharedMemorySize, SMEM_DYN);

    // CSR build
    clear_counts_kernel<<<(NN + 255) / 256, 256>>>();
    hist_kernel<<<(NE + 255) / 256, 256>>>(dst);
    scan_kernel<<<1, 1024>>>();
    fill_kernel<<<(NE + 255) / 256, 256>>>(src, dst);

    // Weight splits (transposed, bf16 hi/lo)
    wprep_kernel<<<64, 256>>>(W1, w1hi, w1lo);
    wprep_kernel<<<64, 256>>>(W2, w2hi, w2lo);

    const int gather_blocks = (NN * 32 + 255) / 256;

    // layer 1
    gather_kernel<<<gather_blocks, 256>>>(x, z);
    mlp_pair_kernel<<<NT, 512, SMEM_DYN>>>(z, w1hi, w1lo, w2hi, w2lo, b1, b2, ha, PADN, 1);
    // layer 2
    gather_kernel<<<gather_blocks, 256>>>(ha, z);
    mlp_pair_kernel<<<NT, 512, SMEM_DYN>>>(z, w1hi, w1lo, w2hi, w2lo, b1, b2, hb, PADN, 1);
    // layer 3 (no final ReLU)
    gather_kernel<<<gather_blocks, 256>>>(hb, z);
    mlp_pair_kernel<<<NT, 512, SMEM_DYN>>>(z, w1hi, w1lo, w2hi, w2lo, b1, b2, out, NN, 0);
}